// round 9
// baseline (speedup 1.0000x reference)
#include <cuda_runtime.h>
#include <cuda_bf16.h>
#include <cstdint>

#define NNODES 20000
#define NEDGES 160000
#define F_IN   512
#define F_HID  512
#define F_OUT  256

// ---------------- scratch ----------------------------------------------------
__device__ int   g_is64;
__device__ int   g_deg[NNODES];
__device__ int   g_rowptr[NNODES + 1];
__device__ int   g_cursor[NNODES];
__device__ int   g_srcs[NEDGES];
__device__ __align__(16) float g_dinv[NNODES];
__device__ __align__(16) float g_h1[(size_t)NNODES * F_HID];
__device__ __align__(16) float g_a1[(size_t)NNODES * F_HID];
__device__ __align__(16) float g_h2[(size_t)NNODES * F_OUT];

// ---------------- preprocessing ---------------------------------------------
__global__ void detect_zero_kernel(const int* ei) {
    const int i = blockIdx.x * blockDim.x + threadIdx.x;
    if (i == 0) {
        int is64 = 1;
        for (int k = 1; k < 64; k += 2)
            if (ei[k] != 0) { is64 = 0; break; }
        g_is64 = is64;
    }
    if (i < NNODES) g_deg[i] = 0;
}

__global__ void deg_count_kernel(const void* ei) {
    const int e = blockIdx.x * blockDim.x + threadIdx.x;
    if (e < NEDGES) {
        int dst;
        if (g_is64) dst = (int)((const long long*)ei)[NEDGES + e];
        else        dst = ((const int*)ei)[NEDGES + e];
        atomicAdd(&g_deg[dst], 1);
    }
}

__global__ void scan_dinv_kernel() {
    __shared__ int part[1024];
    const int t = threadIdx.x;
    const int CH = (NNODES + 1023) / 1024;
    const int base = t * CH;
    int s = 0;
    for (int i = 0; i < CH; i++) {
        int idx = base + i;
        if (idx < NNODES) s += g_deg[idx];
    }
    part[t] = s;
    __syncthreads();
    for (int off = 1; off < 1024; off <<= 1) {
        int v = (t >= off) ? part[t - off] : 0;
        __syncthreads();
        part[t] += v;
        __syncthreads();
    }
    int run = (t > 0) ? part[t - 1] : 0;
    for (int i = 0; i < CH; i++) {
        int idx = base + i;
        if (idx < NNODES) {
            g_rowptr[idx] = run;
            g_cursor[idx] = run;
            g_dinv[idx] = rsqrtf(1.0f + (float)g_deg[idx]);
            run += g_deg[idx];
        }
    }
    if (t == 1023) g_rowptr[NNODES] = part[1023];
}

__global__ void fill_kernel(const void* ei) {
    const int e = blockIdx.x * blockDim.x + threadIdx.x;
    if (e < NEDGES) {
        int src, dst;
        if (g_is64) {
            const long long* p = (const long long*)ei;
            src = (int)p[e]; dst = (int)p[NEDGES + e];
        } else {
            const int* p = (const int*)ei;
            src = p[e]; dst = p[NEDGES + e];
        }
        int pos = atomicAdd(&g_cursor[dst], 1);
        g_srcs[pos] = src;
    }
}

template <int F>
__global__ void scale_rows_kernel(float* __restrict__ h) {
    const int total4 = NNODES * F / 4;
    for (int idx = blockIdx.x * blockDim.x + threadIdx.x; idx < total4;
         idx += gridDim.x * blockDim.x) {
        const int node = idx / (F / 4);
        const float d = g_dinv[node];
        float4 v = reinterpret_cast<float4*>(h)[idx];
        v.x *= d; v.y *= d; v.z *= d; v.w *= d;
        reinterpret_cast<float4*>(h)[idx] = v;
    }
}

// ---------------- tf32 tensor-core GEMM -------------------------------------
// C[M,N] = A[M,K] @ B[K,N] (optionally * dinv[row]).
// Block 128x64, 8 warps (4x2), warp tile 32x32, BK=16, double-buffered smem.
__device__ __forceinline__ uint32_t f2tf32(float f) {
    uint32_t r;
    asm("cvt.rna.tf32.f32 %0, %1;" : "=r"(r) : "f"(f));
    return r;
}

template <bool SCALE_OUT>
__global__ __launch_bounds__(256)
void tf32gemm_kernel(const float* __restrict__ A, const float* __restrict__ B,
                     float* __restrict__ C, int M, int N, int K) {
    constexpr int BM = 128, BN = 64, BK = 16;
    constexpr int AP = BK + 1;    // 17: A row pitch
    constexpr int BP = BN + 4;    // 68: B row pitch
    __shared__ uint32_t As[2][BM][AP];
    __shared__ uint32_t Bs[2][BK][BP];

    const int tid  = threadIdx.x;
    const int wid  = tid >> 5;              // 0..7
    const int lane = tid & 31;
    const int wm = (wid >> 1) * 32;         // warp row offset: 0,32,64,96
    const int wn = (wid & 1) * 32;          // warp col offset: 0,32

    const int block_row = blockIdx.y * BM;
    const int block_col = blockIdx.x * BN;

    // global A: 128 rows x 16 k = 512 float4 -> 2 per thread
    const int a_row = tid >> 1;             // 0..127
    const int a_k8  = (tid & 1) * 8;        // 0 or 8
    const int a_g_row = block_row + a_row;
    const bool a_ok = a_g_row < M;
    const float* a_ptr = A + (size_t)(a_ok ? a_g_row : 0) * K + a_k8;
    // global B: 16 k x 64 n = 256 float4 -> 1 per thread
    const int b_k  = tid >> 4;              // 0..15
    const int b_n4 = (tid & 15) * 4;
    const float* b_ptr = B + (size_t)b_k * N + block_col + b_n4;

    float acc[2][4][4];                     // [mi][ni][c0..c3]
    #pragma unroll
    for (int mi = 0; mi < 2; mi++)
        #pragma unroll
        for (int ni = 0; ni < 4; ni++)
            #pragma unroll
            for (int c = 0; c < 4; c++) acc[mi][ni][c] = 0.f;

    float4 av0, av1, bv;
    auto load_tile = [&](int k0) {
        const float* ap = a_ptr + (size_t)k0 * BK;
        av0 = a_ok ? *reinterpret_cast<const float4*>(ap)
                   : make_float4(0.f, 0.f, 0.f, 0.f);
        av1 = a_ok ? *reinterpret_cast<const float4*>(ap + 4)
                   : make_float4(0.f, 0.f, 0.f, 0.f);
        bv = *reinterpret_cast<const float4*>(b_ptr + (size_t)k0 * BK * N);
    };
    auto store_tile = [&](int buf) {
        As[buf][a_row][a_k8 + 0] = f2tf32(av0.x);
        As[buf][a_row][a_k8 + 1] = f2tf32(av0.y);
        As[buf][a_row][a_k8 + 2] = f2tf32(av0.z);
        As[buf][a_row][a_k8 + 3] = f2tf32(av0.w);
        As[buf][a_row][a_k8 + 4] = f2tf32(av1.x);
        As[buf][a_row][a_k8 + 5] = f2tf32(av1.y);
        As[buf][a_row][a_k8 + 6] = f2tf32(av1.z);
        As[buf][a_row][a_k8 + 7] = f2tf32(av1.w);
        Bs[buf][b_k][b_n4 + 0] = f2tf32(bv.x);
        Bs[buf][b_k][b_n4 + 1] = f2tf32(bv.y);
        Bs[buf][b_k][b_n4 + 2] = f2tf32(bv.z);
        Bs[buf][b_k][b_n4 + 3] = f2tf32(bv.w);
    };

    load_tile(0);
    store_tile(0);
    __syncthreads();

    const int nsteps = K / BK;
    const int qr = lane >> 2;               // t/4: 0..7
    const int qc = lane & 3;                // t%4: 0..3

    for (int k0 = 0; k0 < nsteps; k0++) {
        const int buf = k0 & 1;
        const bool has_next = (k0 + 1) < nsteps;
        if (has_next) load_tile(k0 + 1);

        #pragma unroll
        for (int ks = 0; ks < 2; ks++) {
            const int kb = ks * 8;
            // A fragments for mi=0,1
            uint32_t af[2][4];
            #pragma unroll
            for (int mi = 0; mi < 2; mi++) {
                const int r = wm + mi * 16 + qr;
                af[mi][0] = As[buf][r][kb + qc];
                af[mi][1] = As[buf][r + 8][kb + qc];
                af[mi][2] = As[buf][r][kb + qc + 4];
                af[mi][3] = As[buf][r + 8][kb + qc + 4];
            }
            #pragma unroll
            for (int ni = 0; ni < 4; ni++) {
                const int n = wn + ni * 8 + qr;
                uint32_t b0 = Bs[buf][kb + qc][n];
                uint32_t b1 = Bs[buf][kb + qc + 4][n];
                #pragma unroll
                for (int mi = 0; mi < 2; mi++) {
                    asm volatile(
                        "mma.sync.aligned.m16n8k8.row.col.f32.tf32.tf32.f32 "
                        "{%0,%1,%2,%3}, {%4,%5,%6,%7}, {%8,%9}, {%0,%1,%2,%3};"
                        : "+f"(acc[mi][ni][0]), "+f"(acc[mi][ni][1]),
                          "+f"(acc[mi][ni][2]), "+f"(acc[mi][ni][3])
                        : "r"(af[mi][0]), "r"(af[mi][1]), "r"(af[mi][2]), "r"(af[mi][3]),
                          "r"(b0), "r"(b1));
                }
            }
        }

        if (has_next) {
            __syncthreads();
            store_tile(buf ^ 1);
            __syncthreads();
        }
    }

    // epilogue: c0,c1 = (row qr, cols 2qc, 2qc+1); c2,c3 = row qr+8
    #pragma unroll
    for (int mi = 0; mi < 2; mi++) {
        #pragma unroll
        for (int half = 0; half < 2; half++) {
            const int gr = block_row + wm + mi * 16 + qr + half * 8;
            if (gr < M) {
                const float d = SCALE_OUT ? g_dinv[gr] : 1.0f;
                #pragma unroll
                for (int ni = 0; ni < 4; ni++) {
                    const int gc = block_col + wn + ni * 8 + qc * 2;
                    float2 v;
                    v.x = acc[mi][ni][half * 2 + 0] * d;
                    v.y = acc[mi][ni][half * 2 + 1] * d;
                    *reinterpret_cast<float2*>(C + (size_t)gr * N + gc) = v;
                }
            }
        }
    }
}

// ---------------- pull aggregation over pre-scaled rows (UNCHANGED) ---------
template <int F>
__global__ void aggregate_warp_kernel(const float* __restrict__ h,
                                      const float* __restrict__ bias,
                                      float* __restrict__ out) {
    constexpr int NV = F / 128;
    const int w    = threadIdx.x >> 5;
    const int lane = threadIdx.x & 31;
    const int v = blockIdx.x * 8 + w;
    if (v >= NNODES) return;

    const float dv = g_dinv[v];

    float4 acc[NV];
    {
        const float4* hv = reinterpret_cast<const float4*>(h + (size_t)v * F);
        #pragma unroll
        for (int i = 0; i < NV; i++) acc[i] = __ldg(&hv[lane + 32 * i]);
    }

    const int beg = g_rowptr[v];
    const int end = g_rowptr[v + 1];
    int j = beg;
    for (; j + 4 <= end; j += 4) {
        const int s0 = __ldg(&g_srcs[j + 0]);
        const int s1 = __ldg(&g_srcs[j + 1]);
        const int s2 = __ldg(&g_srcs[j + 2]);
        const int s3 = __ldg(&g_srcs[j + 3]);
        const float4* p0 = reinterpret_cast<const float4*>(h + (size_t)s0 * F);
        const float4* p1 = reinterpret_cast<const float4*>(h + (size_t)s1 * F);
        const float4* p2 = reinterpret_cast<const float4*>(h + (size_t)s2 * F);
        const float4* p3 = reinterpret_cast<const float4*>(h + (size_t)s3 * F);
        #pragma unroll
        for (int i = 0; i < NV; i++) {
            const int c = lane + 32 * i;
            float4 t0 = __ldg(&p0[c]);
            float4 t1 = __ldg(&p1[c]);
            float4 t2 = __ldg(&p2[c]);
            float4 t3 = __ldg(&p3[c]);
            acc[i].x += (t0.x + t1.x) + (t2.x + t3.x);
            acc[i].y += (t0.y + t1.y) + (t2.y + t3.y);
            acc[i].z += (t0.z + t1.z) + (t2.z + t3.z);
            acc[i].w += (t0.w + t1.w) + (t2.w + t3.w);
        }
    }
    for (; j < end; j++) {
        const int s = __ldg(&g_srcs[j]);
        const float4* p = reinterpret_cast<const float4*>(h + (size_t)s * F);
        #pragma unroll
        for (int i = 0; i < NV; i++) {
            float4 t = __ldg(&p[lane + 32 * i]);
            acc[i].x += t.x; acc[i].y += t.y; acc[i].z += t.z; acc[i].w += t.w;
        }
    }

    const float4* bptr = reinterpret_cast<const float4*>(bias);
    float4* optr = reinterpret_cast<float4*>(out + (size_t)v * F);
    #pragma unroll
    for (int i = 0; i < NV; i++) {
        float4 b = bptr[lane + 32 * i];
        float4 o;
        o.x = fmaxf(acc[i].x * dv + b.x, 0.f);
        o.y = fmaxf(acc[i].y * dv + b.y, 0.f);
        o.z = fmaxf(acc[i].z * dv + b.z, 0.f);
        o.w = fmaxf(acc[i].w * dv + b.w, 0.f);
        optr[lane + 32 * i] = o;
    }
}

// ---------------- launch ----------------------------------------------------
// tf32 gemm1 placed at launch index 3 (the ncu capture slot).
extern "C" void kernel_launch(void* const* d_in, const int* in_sizes, int n_in,
                              void* d_out, int out_size) {
    const float* x  = (const float*)d_in[0];
    const void*  ei = d_in[1];
    const float* W1 = (const float*)d_in[2];
    const float* b1 = (const float*)d_in[3];
    const float* W2 = (const float*)d_in[4];
    const float* b2 = (const float*)d_in[5];
    float* out = (float*)d_out;

    detect_zero_kernel<<<(NNODES + 255) / 256, 256>>>((const int*)ei);  // 0
    deg_count_kernel<<<(NEDGES + 255) / 256, 256>>>(ei);                // 1
    scan_dinv_kernel<<<1, 1024>>>();                                    // 2

    {                                                                   // 3 (capture)
        dim3 grid(F_HID / 64, (NNODES + 127) / 128);
        tf32gemm_kernel<false><<<grid, 256>>>(x, W1, g_h1, NNODES, F_HID, F_IN);
    }

    fill_kernel<<<(NEDGES + 255) / 256, 256>>>(ei);                     // 4
    scale_rows_kernel<F_HID><<<2048, 256>>>(g_h1);                      // 5
    aggregate_warp_kernel<F_HID><<<(NNODES + 7) / 8, 256>>>(g_h1, b1, g_a1);  // 6

    {                                                                   // 7
        dim3 grid(F_OUT / 64, (NNODES + 127) / 128);
        tf32gemm_kernel<true><<<grid, 256>>>(g_a1, W2, g_h2, NNODES, F_OUT, F_HID);
    }
    aggregate_warp_kernel<F_OUT><<<(NNODES + 7) / 8, 256>>>(g_h2, b2, out);   // 8
}